// round 12
// baseline (speedup 1.0000x reference)
#include <cuda_runtime.h>
#include <cstdint>

// ---------------------------------------------------------------------------
// HeavyCompressor round 12: occupancy-2 variant. CTA_M=64, 256 threads,
// 8 warps (2m x 4n, warp tile 32x64), KT=32, 2-stage ring (80 KB) -> two
// CTAs co-resident per SM: work-stealing removes wave quantization and the
// partner CTA's MMAs hide barrier/ldsm bubbles.
//   A streams raw fp32 bits via cp.async (HMMA tf32 reads top 19 bits),
//   B pre-converted rna-tf32 in device scratch. Cell swizzle ^= (row & 7).
// ---------------------------------------------------------------------------

constexpr int D_     = 2048;
constexpr int HD_    = 128;
constexpr int CTA_M  = 64;
constexpr int KT     = 32;
constexpr int NK     = D_ / KT;                 // 64
constexpr int A_BYTES = CTA_M * 128;            // 8 KB
constexpr int B_BYTES = 256 * 128;              // 32 KB
constexpr int STAGE_BYTES = A_BYTES + B_BYTES;  // 40 KB
constexpr int EPI_STR = 276;
constexpr int EPI_BYTES = CTA_M * EPI_STR * 4;  // 70656
constexpr int SMEM_BYTES = 2 * STAGE_BYTES;     // 81920 (> epilogue)

__device__ uint32_t g_wtf32[256 * 2048];        // rna-preconverted [wkv;wz]

__device__ __forceinline__ uint32_t f2tf(float f) {
    uint32_t r;
    asm("cvt.rna.tf32.f32 %0, %1;" : "=r"(r) : "f"(f));
    return r;
}
__device__ __forceinline__ uint32_t smem_u32(const void* p) {
    uint32_t a;
    asm("{ .reg .u64 t; cvta.to.shared.u64 t, %1; cvt.u32.u64 %0, t; }" : "=r"(a) : "l"(p));
    return a;
}
__device__ __forceinline__ void cp16(uint32_t dst, const void* src) {
    asm volatile("cp.async.cg.shared.global [%0], [%1], 16;" :: "r"(dst), "l"(src) : "memory");
}
__device__ __forceinline__ void ldsm4(uint32_t* r, uint32_t addr) {
    asm volatile("ldmatrix.sync.aligned.m8n8.x4.shared.b16 {%0,%1,%2,%3}, [%4];"
                 : "=r"(r[0]), "=r"(r[1]), "=r"(r[2]), "=r"(r[3]) : "r"(addr));
}
__device__ __forceinline__ void mma_tf32(float* c, uint32_t a0, uint32_t a1,
                                         uint32_t a2, uint32_t a3,
                                         uint32_t b0, uint32_t b1) {
    asm volatile(
        "mma.sync.aligned.m16n8k8.row.col.f32.tf32.tf32.f32 "
        "{%0,%1,%2,%3}, {%4,%5,%6,%7}, {%8,%9}, {%0,%1,%2,%3};"
        : "+f"(c[0]), "+f"(c[1]), "+f"(c[2]), "+f"(c[3])
        : "r"(a0), "r"(a1), "r"(a2), "r"(a3), "r"(b0), "r"(b1));
}

__global__ void convert_w(const float4* __restrict__ wkv, const float4* __restrict__ wz) {
    int i = blockIdx.x * blockDim.x + threadIdx.x;      // 0..131071 float4s
    int row = i >> 9, c4 = i & 511;
    float4 v = (row < 128) ? wkv[row * 512 + c4] : wz[(row - 128) * 512 + c4];
    ((uint4*)g_wtf32)[i] = make_uint4(f2tf(v.x), f2tf(v.y), f2tf(v.z), f2tf(v.w));
}

__global__ __launch_bounds__(256, 2)
void heavy_compressor_v12(const float* __restrict__ h,
                          const float* __restrict__ bias,
                          float* __restrict__ out,
                          int write_second, int out_half)
{
    extern __shared__ char smem[];
    const uint32_t sbase = smem_u32(smem);

    const int tid  = threadIdx.x;
    const int wid  = tid >> 5;
    const int lane = tid & 31;
    const int g    = lane >> 2;
    const int tg   = lane & 3;
    const int warp_m = wid & 1;            // 2 x 32 rows
    const int warp_n = wid >> 1;           // 4 x 64 cols
    const long long row0 = (long long)blockIdx.x * CTA_M;

    float acc[2][8][4];                    // 64 floats
#pragma unroll
    for (int mi = 0; mi < 2; ++mi)
#pragma unroll
        for (int ni = 0; ni < 8; ++ni)
#pragma unroll
            for (int j = 0; j < 4; ++j) acc[mi][ni][j] = 0.f;

    // ---- A cp.async: 512 cells/stage, 2 per thread (raw fp32 bits) ----
    const int ar0 = tid >> 3, akc0 = tid & 7;                       // i=0
    const int ar1 = (tid + 256) >> 3;                               // i=1
    const float* asrc0 = h + (row0 + ar0) * D_ + akc0 * 4;
    const float* asrc1 = h + (row0 + ar1) * D_ + akc0 * 4;
    const uint32_t adst0 = ar0 * 128 + ((akc0 ^ (ar0 & 7)) * 16);
    const uint32_t adst1 = ar1 * 128 + ((akc0 ^ (ar1 & 7)) * 16);

    // ---- B cp.async: 2048 cells/stage, 8 per thread, affine in i ----
    // idx = i*256 + tid ; brow = i*32 + (tid>>3) ; kc = tid & 7
    const int btr = tid >> 3;                           // 0..31
    const int bkc = tid & 7;
    const uint32_t* bsrc0 = g_wtf32 + btr * 2048 + bkc * 4;            // + i*32*2048
    const uint32_t bdst0 = A_BYTES + btr * 128 + ((bkc ^ (btr & 7)) * 16); // + i*4096

    auto cp_stage = [&](int s) {
        const uint32_t base = sbase + (s & 1) * STAGE_BYTES;
        const int k0 = s * KT;
        cp16(base + adst0, asrc0 + k0);
        cp16(base + adst1, asrc1 + k0);
        const uint32_t* bs = bsrc0 + k0;
#pragma unroll
        for (int i = 0; i < 8; ++i)
            cp16(base + bdst0 + i * 4096, bs + i * 65536);
        asm volatile("cp.async.commit_group;" ::: "memory");
    };

    // ---- ldsm lane-constant offsets (cell ^= row&7) ----
    const int row16  = (lane & 7) | (((lane >> 3) & 1) << 3);
    const int hiA    = lane >> 4;
    const int brow16 = (lane & 7) | ((lane >> 4) << 3);
    const int hiB    = (lane >> 3) & 1;
    const int l7     = lane & 7;
    int offA[4], offB[4];
#pragma unroll
    for (int ks = 0; ks < 4; ++ks) {
        offA[ks] = row16  * 128 + (((2 * ks + hiA) ^ l7) * 16);
        offB[ks] = brow16 * 128 + (((2 * ks + hiB) ^ l7) * 16);
    }
    const uint32_t aW = warp_m * 4096;                  // 32 rows * 128B
    const uint32_t bW = A_BYTES + warp_n * 8192;        // 64 rows * 128B

    // ---- prologue ----
    cp_stage(0);

    // ---- mainloop: one barrier per tile ----
#pragma unroll 1
    for (int t = 0; t < NK; ++t) {
        asm volatile("cp.async.wait_group 0;" ::: "memory");
        __syncthreads();

        if (t + 1 < NK) cp_stage(t + 1);

        const uint32_t cs = sbase + (t & 1) * STAGE_BYTES;
#pragma unroll
        for (int ks = 0; ks < 4; ++ks) {
            uint32_t a[2][4], b[4][4];
#pragma unroll
            for (int mi = 0; mi < 2; ++mi)
                ldsm4(a[mi], cs + aW + mi * 2048 + offA[ks]);
#pragma unroll
            for (int np = 0; np < 4; ++np)
                ldsm4(b[np], cs + bW + np * 2048 + offB[ks]);
#pragma unroll
            for (int mi = 0; mi < 2; ++mi)
#pragma unroll
                for (int ni = 0; ni < 8; ++ni)
                    mma_tf32(acc[mi][ni],
                             a[mi][0], a[mi][1], a[mi][2], a[mi][3],
                             b[ni >> 1][(ni & 1) * 2], b[ni >> 1][(ni & 1) * 2 + 1]);
        }
    }

    // ---- epilogue: accums -> smem, windowed softmax-compress ----
    float* epi = (float*)smem;
    __syncthreads();
#pragma unroll
    for (int mi = 0; mi < 2; ++mi)
#pragma unroll
        for (int ni = 0; ni < 8; ++ni) {
            int m0 = warp_m * 32 + mi * 16 + g;
            int n0 = warp_n * 64 + ni * 8 + 2 * tg;
            *(float2*)(epi + m0 * EPI_STR + n0)       = make_float2(acc[mi][ni][0], acc[mi][ni][1]);
            *(float2*)(epi + (m0 + 8) * EPI_STR + n0) = make_float2(acc[mi][ni][2], acc[mi][ni][3]);
        }
    __syncthreads();

    const int win = tid >> 5;            // 8 windows of 8 rows
    float zb[8][4], cc[8][4];
#pragma unroll
    for (int r = 0; r < 8; ++r) {
        const float* rp = epi + (win * 8 + r) * EPI_STR;
        float4 c4 = *(const float4*)(rp + lane * 4);
        float4 z4 = *(const float4*)(rp + HD_ + lane * 4);
        float4 b4 = *(const float4*)(bias + r * HD_ + lane * 4);
        cc[r][0] = c4.x; cc[r][1] = c4.y; cc[r][2] = c4.z; cc[r][3] = c4.w;
        zb[r][0] = z4.x + b4.x; zb[r][1] = z4.y + b4.y;
        zb[r][2] = z4.z + b4.z; zb[r][3] = z4.w + b4.w;
    }
    float res[4];
#pragma unroll
    for (int i = 0; i < 4; ++i) {
        float mx = zb[0][i];
#pragma unroll
        for (int r = 1; r < 8; ++r) mx = fmaxf(mx, zb[r][i]);
        float s = 0.f, a = 0.f;
#pragma unroll
        for (int r = 0; r < 8; ++r) {
            float e = __expf(zb[r][i] - mx);
            s += e;
            a = fmaf(e, cc[r][i], a);
        }
        res[i] = a / s;
    }
    const long long w = (long long)blockIdx.x * 8 + win;
    float4 v = make_float4(res[0], res[1], res[2], res[3]);
    float* dst = out + w * HD_ + lane * 4;
    *(float4*)dst = v;
    if (write_second) *(float4*)(dst + out_half) = v;
}

extern "C" void kernel_launch(void* const* d_in, const int* in_sizes, int n_in,
                              void* d_out, int out_size)
{
    const float* h    = (const float*)d_in[0];
    const float* wkv  = (const float*)d_in[1];
    const float* wz   = (const float*)d_in[2];
    const float* bias = (const float*)d_in[3];

    const int rows = in_sizes[0] / D_;              // 32768
    const int base = (rows / 8) * HD_;              // 524288
    const int write_second = (out_size >= 2 * base) ? 1 : 0;

    convert_w<<<512, 256>>>((const float4*)wkv, (const float4*)wz);

    cudaFuncSetAttribute(heavy_compressor_v12,
                         cudaFuncAttributeMaxDynamicSharedMemorySize, SMEM_BYTES);
    heavy_compressor_v12<<<rows / CTA_M, 256, SMEM_BYTES>>>(
        h, bias, (float*)d_out, write_second, base);
}